// round 1
// baseline (speedup 1.0000x reference)
#include <cuda_runtime.h>
#include <math.h>

#define NF 3072
#define LDIM 128
#define NBATCH 8192

// ---------------- device scratch (no allocations allowed) ----------------
__device__ float g_M[LDIM * LDIM];      // M = W^T W + sigma^2 I
__device__ float g_Lp[8128];            // strict lower triangle of L, packed
__device__ float g_invdiag[LDIM];       // 1 / L[j][j]
__device__ float g_V[NF * LDIM];        // V = W L^{-T}
__device__ float g_const;               // -0.5*(n log2pi + (n-k) log s2 + logdetM)
__device__ float g_inv_sigma2;

// ---------------- K1: M = W^T W + sigma^2 I ----------------
__global__ void k_M(const float* __restrict__ W, const float* __restrict__ log_var) {
    __shared__ float Wa[32][16];
    __shared__ float Wb[32][16];
    const int ti = threadIdx.x, tj = threadIdx.y;
    const int i0 = blockIdx.x * 16, j0 = blockIdx.y * 16;
    float acc = 0.f;
    for (int k0 = 0; k0 < NF; k0 += 32) {
        Wa[tj][ti]      = W[(k0 + tj) * LDIM + i0 + ti];
        Wa[tj + 16][ti] = W[(k0 + tj + 16) * LDIM + i0 + ti];
        Wb[tj][ti]      = W[(k0 + tj) * LDIM + j0 + ti];
        Wb[tj + 16][ti] = W[(k0 + tj + 16) * LDIM + j0 + ti];
        __syncthreads();
#pragma unroll
        for (int k = 0; k < 32; k++) acc += Wa[k][ti] * Wb[k][tj];
        __syncthreads();
    }
    const int gi = i0 + ti, gj = j0 + tj;
    if (gi == gj) acc += expf(log_var[0]);
    g_M[gi * LDIM + gj] = acc;
}

// ---------------- K2: single-block packed Cholesky + logdet ----------------
__global__ void k_chol(const float* __restrict__ log_var) {
    __shared__ float Ap[8256];   // lower triangle incl diag, packed: off(j)=j(j+1)/2
    __shared__ float col[LDIM];
    __shared__ float red[LDIM];
    const int tid = threadIdx.x;             // 128 threads, thread = row
    const int off = tid * (tid + 1) / 2;
    for (int c = 0; c <= tid; c++) Ap[off + c] = g_M[tid * LDIM + c];
    __syncthreads();
    for (int i = 0; i < LDIM; i++) {
        const int ii = i * (i + 1) / 2;
        float p = Ap[ii + i];
        float d = sqrtf(p);
        float inv = 1.0f / d;
        __syncthreads();                     // everyone read pivot before writes
        if (tid > i) {
            float v = Ap[off + i] * inv;
            Ap[off + i] = v;
            col[tid] = v;
        } else if (tid == i) {
            Ap[off + i] = d;
        }
        __syncthreads();
        if (tid > i) {
            float f = col[tid];
            for (int k = i + 1; k <= tid; k++) Ap[off + k] -= f * col[k];
        }
        __syncthreads();
    }
    float dv = Ap[off + tid];
    g_invdiag[tid] = 1.0f / dv;
    red[tid] = logf(dv);
    const int soff = tid * (tid - 1) / 2;    // strict-lower packed output
    for (int c = 0; c < tid; c++) g_Lp[soff + c] = Ap[off + c];
    __syncthreads();
    if (tid < 64) red[tid] += red[tid + 64];
    __syncthreads();
    if (tid < 32) {
        float s = red[tid] + red[tid + 32];
#pragma unroll
        for (int o = 16; o > 0; o >>= 1) s += __shfl_xor_sync(0xffffffffu, s, o);
        if (tid == 0) {
            float logdetM = 2.0f * s;
            float lv = log_var[0];
            float s2 = expf(lv);
            g_inv_sigma2 = 1.0f / s2;
            g_const = -0.5f * ((float)(3072.0 * 1.8378770664093454)  // n*log(2pi)
                               + 2944.0f * lv                          // (n-k)*log s2
                               + logdetM);
        }
    }
}

// ---------------- K3: V = W L^{-T}  (3072 independent triangular solves) ----------------
__global__ void k_trisolve(const float* __restrict__ W) {
    __shared__ float Ls[8128];          // strict lower of L, packed
    __shared__ float acc[LDIM * 32];    // acc[k*32 + tid]
    const int tid = threadIdx.x;        // 32 threads, one W-row each
    for (int t = tid; t < 8128; t += 32) Ls[t] = g_Lp[t];
    const int row = blockIdx.x * 32 + tid;
    const float* wrow = W + row * LDIM;
    for (int k = 0; k < LDIM; k++) acc[k * 32 + tid] = wrow[k];
    __syncthreads();
    for (int j = LDIM - 1; j >= 0; j--) {
        float v = acc[j * 32 + tid] * __ldg(&g_invdiag[j]);
        acc[j * 32 + tid] = v;
        const float* Lr = Ls + (j * (j - 1)) / 2;   // row j of L, cols < j
        for (int jj = 0; jj < j; jj++) acc[jj * 32 + tid] -= Lr[jj] * v;
    }
    float* vout = g_V + row * LDIM;
    for (int k = 0; k < LDIM; k++) vout[k] = acc[k * 32 + tid];
}

// ---------------- K4: fused GEMM + row norms + output ----------------
// tile: 64 rows x 128 cols (full N), KT=16, 256 threads, micro-tile 8x4.
#define K4_COMPUTE()                                                            \
    _Pragma("unroll")                                                           \
    for (int k = 0; k < 16; k++) {                                              \
        float4 b  = *(const float4*)&Vs[k][tx * 4];                             \
        float4 a0 = *(const float4*)&As[k][ty * 8];                             \
        float4 a1 = *(const float4*)&As[k][ty * 8 + 4];                         \
        float a[8] = {a0.x, a0.y, a0.z, a0.w, a1.x, a1.y, a1.z, a1.w};          \
        _Pragma("unroll")                                                       \
        for (int i = 0; i < 8; i++) {                                           \
            acc[i][0] += a[i] * b.x;                                            \
            acc[i][1] += a[i] * b.y;                                            \
            acc[i][2] += a[i] * b.z;                                            \
            acc[i][3] += a[i] * b.w;                                            \
        }                                                                       \
    }

#define K4_STORE()                                                              \
    {                                                                           \
        float r0 = xv.x - mv.x, r1 = xv.y - mv.y;                               \
        float r2 = xv.z - mv.z, r3 = xv.w - mv.w;                               \
        ssp += r0 * r0 + r1 * r1 + r2 * r2 + r3 * r3;                           \
        As[lseg * 4 + 0][ldr] = r0;                                             \
        As[lseg * 4 + 1][ldr] = r1;                                             \
        As[lseg * 4 + 2][ldr] = r2;                                             \
        As[lseg * 4 + 3][ldr] = r3;                                             \
        *(float4*)&Vs[vk0][vc]     = va;                                        \
        *(float4*)&Vs[vk0 + 8][vc] = vb;                                        \
    }

__global__ __launch_bounds__(256, 1) void k_main(const float* __restrict__ X,
                                                 const float* __restrict__ mean,
                                                 float* __restrict__ out) {
    __shared__ float As[16][72];     // r values, [k][row], padded
    __shared__ float Vs[16][128];    // V tile, [k][col]
    __shared__ float ssred[4][64];
    const int tid  = threadIdx.x;
    const int tx   = tid & 31, ty = tid >> 5;      // compute layout 32x8
    const int ldr  = tid >> 2, lseg = tid & 3;     // X loader layout 64x4
    const int row0 = blockIdx.x * 64;
    const int vk0  = tid >> 5, vc = (tid & 31) * 4; // V loader
    const float* xptr = X + (size_t)(row0 + ldr) * NF + lseg * 4;

    float acc[8][4];
#pragma unroll
    for (int i = 0; i < 8; i++)
#pragma unroll
        for (int j = 0; j < 4; j++) acc[i][j] = 0.f;
    float ssp = 0.f;

    float4 xv, mv, va, vb;
    // prologue: tile 0
    xv = *(const float4*)(xptr);
    mv = *(const float4*)(mean + lseg * 4);
    va = *(const float4*)(g_V + vk0 * LDIM + vc);
    vb = *(const float4*)(g_V + (vk0 + 8) * LDIM + vc);
    K4_STORE();
    __syncthreads();

    for (int t = 1; t < NF / 16; t++) {
        const int k0 = t * 16;
        xv = *(const float4*)(xptr + k0);
        mv = *(const float4*)(mean + k0 + lseg * 4);
        va = *(const float4*)(g_V + (k0 + vk0) * LDIM + vc);
        vb = *(const float4*)(g_V + (k0 + vk0 + 8) * LDIM + vc);
        K4_COMPUTE();            // consume current smem while loads in flight
        __syncthreads();
        K4_STORE();
        __syncthreads();
    }
    K4_COMPUTE();                // last tile

    ssred[lseg][ldr] = ssp;
    __syncthreads();

    float ysq[8];
#pragma unroll
    for (int i = 0; i < 8; i++) {
        float s = acc[i][0] * acc[i][0] + acc[i][1] * acc[i][1]
                + acc[i][2] * acc[i][2] + acc[i][3] * acc[i][3];
#pragma unroll
        for (int o = 16; o > 0; o >>= 1) s += __shfl_xor_sync(0xffffffffu, s, o);
        ysq[i] = s;
    }
    if (tx == 0) {
        const float cst = g_const, is2 = g_inv_sigma2;
#pragma unroll
        for (int i = 0; i < 8; i++) {
            const int r = ty * 8 + i;
            float ss = ssred[0][r] + ssred[1][r] + ssred[2][r] + ssred[3][r];
            out[row0 + r] = cst - 0.5f * (ss - ysq[i]) * is2;
        }
    }
}

// ---------------- launch ----------------
extern "C" void kernel_launch(void* const* d_in, const int* in_sizes, int n_in,
                              void* d_out, int out_size) {
    const float* X    = (const float*)d_in[0];   // [8192, 3072]
    const float* W    = (const float*)d_in[1];   // [3072, 128]
    const float* lv   = (const float*)d_in[2];   // [1]
    const float* mean = (const float*)d_in[3];   // [3072]
    float* out = (float*)d_out;                  // [8192]

    k_M<<<dim3(8, 8), dim3(16, 16)>>>(W, lv);
    k_chol<<<1, 128>>>(lv);
    k_trisolve<<<96, 32>>>(W);
    k_main<<<128, 256>>>(X, mean, out);
}

// round 5
// speedup vs baseline: 1.6624x; 1.6624x over previous
#include <cuda_runtime.h>
#include <math.h>

#define NF 3072
#define LDIM 128
#define NBATCH 8192

typedef unsigned long long ull;

// ---------------- device scratch (no allocations allowed) ----------------
__device__ float g_Mpart[16][LDIM * LDIM];  // K-split partials of W^T W
__device__ float g_M[LDIM * LDIM];          // summed M (pre-diag-add)
__device__ float g_Lp[8128];                // strict lower triangle of L, packed
__device__ float g_invdiag[LDIM];           // 1 / L[j][j]
__device__ float g_LB[LDIM * LDIM];         // g_LB[k][j] = (L^-1)[j][k]  (B operand for V gemm)
__device__ float g_V[NF * LDIM];            // V = W L^{-T}
__device__ float g_const;
__device__ float g_inv_sigma2;

// ---------------- f32x2 helpers ----------------
__device__ __forceinline__ ull pack2(float x) {
    ull r; asm("mov.b64 %0, {%1, %1};" : "=l"(r) : "f"(x)); return r;
}
__device__ __forceinline__ void ffma2(ull& d, ull a, ull b) {
    asm("fma.rn.f32x2 %0, %1, %2, %0;" : "+l"(d) : "l"(a), "l"(b));
}
__device__ __forceinline__ void unpack2(ull v, float& lo, float& hi) {
    asm("mov.b64 {%0, %1}, %2;" : "=f"(lo), "=f"(hi) : "l"(v));
}

// ---------------- K1: partial W^T W, K-split, no atomics ----------------
// grid (2,2,16): tile 64x64 out, K-chunk 192. 256 thr = 16x16, micro 4x4.
__global__ __launch_bounds__(256, 1) void k_M(const float* __restrict__ W) {
    __shared__ __align__(16) float Wa[2][16][68];
    __shared__ __align__(16) float Wb[2][16][68];
    const int tid = threadIdx.x;
    const int ti = tid & 15, tj = tid >> 4;
    const int lf = tid >> 4, li = (tid & 15) * 4;
    const int i0 = blockIdx.x * 64, j0 = blockIdx.y * 64;
    const int kb = blockIdx.z * 192;
    float acc[4][4] = {};

    float4 a4 = *(const float4*)&W[(size_t)(kb + lf) * LDIM + i0 + li];
    float4 b4 = *(const float4*)&W[(size_t)(kb + lf) * LDIM + j0 + li];
    *(float4*)&Wa[0][lf][li] = a4;
    *(float4*)&Wb[0][lf][li] = b4;
    __syncthreads();

    for (int t = 0; t < 12; t++) {
        const int cb = t & 1, nb = cb ^ 1;
        float4 na, nbv;
        if (t < 11) {
            na  = *(const float4*)&W[(size_t)(kb + (t + 1) * 16 + lf) * LDIM + i0 + li];
            nbv = *(const float4*)&W[(size_t)(kb + (t + 1) * 16 + lf) * LDIM + j0 + li];
        }
#pragma unroll
        for (int k = 0; k < 16; k++) {
            float4 av = *(const float4*)&Wa[cb][k][ti * 4];
            float4 bv = *(const float4*)&Wb[cb][k][tj * 4];
            float aa[4] = {av.x, av.y, av.z, av.w};
            float bb[4] = {bv.x, bv.y, bv.z, bv.w};
#pragma unroll
            for (int a = 0; a < 4; a++)
#pragma unroll
                for (int b = 0; b < 4; b++) acc[a][b] += aa[a] * bb[b];
        }
        if (t < 11) {
            *(float4*)&Wa[nb][lf][li] = na;
            *(float4*)&Wb[nb][lf][li] = nbv;
        }
        __syncthreads();
    }
    float* dst = g_Mpart[blockIdx.z];
#pragma unroll
    for (int a = 0; a < 4; a++)
#pragma unroll
        for (int b = 0; b < 4; b++)
            dst[(i0 + ti * 4 + a) * LDIM + j0 + tj * 4 + b] = acc[a][b];
}

// ---------------- K2: deterministic partial sum ----------------
__global__ void k_Msum() {
    const int idx = blockIdx.x * 256 + threadIdx.x;
    float s = 0.f;
#pragma unroll
    for (int p = 0; p < 16; p++) s += g_Mpart[p][idx];
    g_M[idx] = s;
}

// ---------------- K3: single-block packed Cholesky (2 threads / row) ----------------
__global__ void k_chol(const float* __restrict__ log_var) {
    __shared__ float Ap[8256];
    __shared__ float col[LDIM];
    __shared__ float red[LDIM];
    const int tid = threadIdx.x;
    const int row = tid & 127, half = tid >> 7;
    const int off = row * (row + 1) / 2;
    const float lv = log_var[0];
    const float s2 = expf(lv);
    for (int c = half; c <= row; c += 2)
        Ap[off + c] = g_M[row * LDIM + c] + (c == row ? s2 : 0.f);
    __syncthreads();
    for (int i = 0; i < LDIM; i++) {
        const int ii = i * (i + 1) / 2;
        float d = sqrtf(Ap[ii + i]);
        float inv = 1.0f / d;
        __syncthreads();                 // all read pivot before writes
        if (half == 0) {
            if (row > i) {
                float v = Ap[off + i] * inv;
                Ap[off + i] = v;
                col[row] = v;
            } else if (row == i) {
                Ap[off + i] = d;
            }
        }
        __syncthreads();
        if (row > i) {
            const float f = col[row];
            for (int k = i + 1 + half; k <= row; k += 2) Ap[off + k] -= f * col[k];
        }
        __syncthreads();
    }
    if (half == 0) {
        float dv = Ap[off + row];
        g_invdiag[row] = 1.0f / dv;
        red[row] = logf(dv);
    }
    {
        const int soff = row * (row - 1) / 2;
        for (int c = half; c < row; c += 2) g_Lp[soff + c] = Ap[off + c];
    }
    __syncthreads();
    if (tid < 64) red[tid] += red[tid + 64];
    __syncthreads();
    if (tid < 32) {
        float s = red[tid] + red[tid + 32];
#pragma unroll
        for (int o = 16; o > 0; o >>= 1) s += __shfl_xor_sync(0xffffffffu, s, o);
        if (tid == 0) {
            float logdetM = 2.0f * s;
            g_inv_sigma2 = 1.0f / s2;
            g_const = -0.5f * ((float)(3072.0 * 1.8378770664093454)
                               + 2944.0f * lv
                               + logdetM);
        }
    }
}

// ---------------- K4: explicit L^{-1}, one column per block ----------------
__global__ void k_linv() {
    __shared__ float Ls[8128];
    __shared__ float xd[LDIM];
    __shared__ float x[LDIM];
    const int c = blockIdx.x, lane = threadIdx.x;
    for (int i = lane; i < 8128; i += 32) Ls[i] = g_Lp[i];
    for (int i = lane; i < LDIM; i += 32) xd[i] = g_invdiag[i];
    __syncwarp();
    if (lane == 0) x[c] = xd[c];
    __syncwarp();
    for (int r = c + 1; r < LDIM; r++) {
        const float* Lr = Ls + ((r * (r - 1)) >> 1);
        float s = 0.f;
        for (int k = c + lane; k < r; k += 32) s += Lr[k] * x[k];
#pragma unroll
        for (int o = 16; o > 0; o >>= 1) s += __shfl_xor_sync(0xffffffffu, s, o);
        if (lane == 0) x[r] = -s * xd[r];
        __syncwarp();
    }
    // g_LB[k][j] = Linv[j][k] ; block c supplies k = c row: g_LB[c][j] = x_c[j]
    for (int j = lane; j < LDIM; j += 32) g_LB[c * LDIM + j] = (j < c) ? 0.f : x[j];
}

// ---------------- K5: V = W * L^{-T}  (GEMM, 48 blocks) ----------------
__global__ __launch_bounds__(256, 1) void k_V(const float* __restrict__ W) {
    __shared__ __align__(16) float As[2][16][68];
    __shared__ __align__(16) float Bs[2][16][128];
    const int tid = threadIdx.x;
    const int tx = tid & 31, ty = tid >> 5;
    const int ldr = tid >> 2, lseg = tid & 3;
    const int vk = tid >> 4, vj = (tid & 15) * 8;
    const int f0 = blockIdx.x * 64;
    const float* wptr = W + (size_t)(f0 + ldr) * LDIM + lseg * 4;

    ull acc[4][4];
#pragma unroll
    for (int i = 0; i < 4; i++)
#pragma unroll
        for (int j = 0; j < 4; j++) acc[i][j] = 0ull;

    float4 xv = *(const float4*)(wptr);
    float4 va = *(const float4*)(g_LB + vk * LDIM + vj);
    float4 vb = *(const float4*)(g_LB + vk * LDIM + vj + 4);
    {
        As[0][lseg * 4 + 0][ldr] = xv.x; As[0][lseg * 4 + 1][ldr] = xv.y;
        As[0][lseg * 4 + 2][ldr] = xv.z; As[0][lseg * 4 + 3][ldr] = xv.w;
        *(float4*)&Bs[0][vk][vj] = va; *(float4*)&Bs[0][vk][vj + 4] = vb;
    }
    __syncthreads();

    for (int t = 0; t < 8; t++) {
        const int cb = t & 1, nb = cb ^ 1;
        if (t < 7) {
            const int k0 = (t + 1) * 16;
            xv = *(const float4*)(wptr + k0);
            va = *(const float4*)(g_LB + (k0 + vk) * LDIM + vj);
            vb = *(const float4*)(g_LB + (k0 + vk) * LDIM + vj + 4);
        }
#pragma unroll
        for (int k = 0; k < 16; k++) {
            float4 b4 = *(const float4*)&Bs[cb][k][tx * 4];
            ull b0 = pack2(b4.x), b1 = pack2(b4.y), b2 = pack2(b4.z), b3 = pack2(b4.w);
            ulonglong2 q0 = *(const ulonglong2*)&As[cb][k][ty * 8];
            ulonglong2 q1 = *(const ulonglong2*)&As[cb][k][ty * 8 + 4];
            ull p[4] = {q0.x, q0.y, q1.x, q1.y};
#pragma unroll
            for (int rp = 0; rp < 4; rp++) {
                ffma2(acc[rp][0], p[rp], b0);
                ffma2(acc[rp][1], p[rp], b1);
                ffma2(acc[rp][2], p[rp], b2);
                ffma2(acc[rp][3], p[rp], b3);
            }
        }
        if (t < 7) {
            As[nb][lseg * 4 + 0][ldr] = xv.x; As[nb][lseg * 4 + 1][ldr] = xv.y;
            As[nb][lseg * 4 + 2][ldr] = xv.z; As[nb][lseg * 4 + 3][ldr] = xv.w;
            *(float4*)&Bs[nb][vk][vj] = va; *(float4*)&Bs[nb][vk][vj + 4] = vb;
        }
        __syncthreads();
    }
#pragma unroll
    for (int rp = 0; rp < 4; rp++)
#pragma unroll
        for (int c = 0; c < 4; c++) {
            float lo, hi;
            unpack2(acc[rp][c], lo, hi);
            g_V[(size_t)(f0 + ty * 8 + 2 * rp) * LDIM + tx * 4 + c] = lo;
            g_V[(size_t)(f0 + ty * 8 + 2 * rp + 1) * LDIM + tx * 4 + c] = hi;
        }
}

// ---------------- K6: fused big GEMM + row norms + output ----------------
// tile 64 rows x 128 cols, KT=16, 256 thr (32x8), micro 8x4 with f32x2 row pairs.
__global__ __launch_bounds__(256, 1) void k_main(const float* __restrict__ X,
                                                 const float* __restrict__ mean,
                                                 float* __restrict__ out) {
    __shared__ __align__(16) float As[2][16][68];
    __shared__ __align__(16) float Vs[2][16][128];
    __shared__ float ssred[4][64];
    const int tid = threadIdx.x;
    const int tx = tid & 31, ty = tid >> 5;
    const int ldr = tid >> 2, lseg = tid & 3;
    const int vk = tid >> 4, vj = (tid & 15) * 8;
    const int row0 = blockIdx.x * 64;
    const float* xptr = X + (size_t)(row0 + ldr) * NF + lseg * 4;

    ull acc[4][4];
#pragma unroll
    for (int i = 0; i < 4; i++)
#pragma unroll
        for (int j = 0; j < 4; j++) acc[i][j] = 0ull;
    float ssp = 0.f;

    float4 xv = *(const float4*)(xptr);
    float4 mv = *(const float4*)(mean + lseg * 4);
    float4 va = *(const float4*)(g_V + vk * LDIM + vj);
    float4 vb = *(const float4*)(g_V + vk * LDIM + vj + 4);
    {
        float r0 = xv.x - mv.x, r1 = xv.y - mv.y, r2 = xv.z - mv.z, r3 = xv.w - mv.w;
        ssp += r0 * r0 + r1 * r1 + r2 * r2 + r3 * r3;
        As[0][lseg * 4 + 0][ldr] = r0; As[0][lseg * 4 + 1][ldr] = r1;
        As[0][lseg * 4 + 2][ldr] = r2; As[0][lseg * 4 + 3][ldr] = r3;
        *(float4*)&Vs[0][vk][vj] = va; *(float4*)&Vs[0][vk][vj + 4] = vb;
    }
    __syncthreads();

    for (int t = 0; t < NF / 16; t++) {
        const int cb = t & 1, nb = cb ^ 1;
        if (t < NF / 16 - 1) {
            const int k0 = (t + 1) * 16;
            xv = *(const float4*)(xptr + k0);
            mv = *(const float4*)(mean + k0 + lseg * 4);
            va = *(const float4*)(g_V + (size_t)(k0 + vk) * LDIM + vj);
            vb = *(const float4*)(g_V + (size_t)(k0 + vk) * LDIM + vj + 4);
        }
#pragma unroll
        for (int k = 0; k < 16; k++) {
            float4 b4 = *(const float4*)&Vs[cb][k][tx * 4];
            ull b0 = pack2(b4.x), b1 = pack2(b4.y), b2 = pack2(b4.z), b3 = pack2(b4.w);
            ulonglong2 q0 = *(const ulonglong2*)&As[cb][k][ty * 8];
            ulonglong2 q1 = *(const ulonglong2*)&As[cb][k][ty * 8 + 4];
            ull p[4] = {q0.x, q0.y, q1.x, q1.y};
#pragma unroll
            for (int rp = 0; rp < 4; rp++) {
                ffma2(acc[rp][0], p[rp], b0);
                ffma2(acc[rp][1], p[rp], b1);
                ffma2(acc[rp][2], p[rp], b2);
                ffma2(acc[rp][3], p[rp], b3);
            }
        }
        if (t < NF / 16 - 1) {
            float r0 = xv.x - mv.x, r1 = xv.y - mv.y, r2 = xv.z - mv.z, r3 = xv.w - mv.w;
            ssp += r0 * r0 + r1 * r1 + r2 * r2 + r3 * r3;
            As[nb][lseg * 4 + 0][ldr] = r0; As[nb][lseg * 4 + 1][ldr] = r1;
            As[nb][lseg * 4 + 2][ldr] = r2; As[nb][lseg * 4 + 3][ldr] = r3;
            *(float4*)&Vs[nb][vk][vj] = va; *(float4*)&Vs[nb][vk][vj + 4] = vb;
        }
        __syncthreads();
    }

    ssred[lseg][ldr] = ssp;
    __syncthreads();

    float ys[8];
#pragma unroll
    for (int i = 0; i < 8; i++) ys[i] = 0.f;
#pragma unroll
    for (int rp = 0; rp < 4; rp++)
#pragma unroll
        for (int c = 0; c < 4; c++) {
            float lo, hi;
            unpack2(acc[rp][c], lo, hi);
            ys[2 * rp]     += lo * lo;
            ys[2 * rp + 1] += hi * hi;
        }
#pragma unroll
    for (int i = 0; i < 8; i++) {
        float s = ys[i];
#pragma unroll
        for (int o = 16; o > 0; o >>= 1) s += __shfl_xor_sync(0xffffffffu, s, o);
        ys[i] = s;
    }
    if (tx == 0) {
        const float cst = g_const, is2 = g_inv_sigma2;
#pragma unroll
        for (int i = 0; i < 8; i++) {
            const int r = ty * 8 + i;
            float ss = ssred[0][r] + ssred[1][r] + ssred[2][r] + ssred[3][r];
            out[row0 + r] = cst - 0.5f * (ss - ys[i]) * is2;
        }
    }
}

// ---------------- launch ----------------
extern "C" void kernel_launch(void* const* d_in, const int* in_sizes, int n_in,
                              void* d_out, int out_size) {
    const float* X    = (const float*)d_in[0];   // [8192, 3072]
    const float* W    = (const float*)d_in[1];   // [3072, 128]
    const float* lv   = (const float*)d_in[2];   // [1]
    const float* mean = (const float*)d_in[3];   // [3072]
    float* out = (float*)d_out;                  // [8192]

    k_M<<<dim3(2, 2, 16), 256>>>(W);
    k_Msum<<<64, 256>>>();
    k_chol<<<1, 256>>>(lv);
    k_linv<<<128, 32>>>();
    k_V<<<48, 256>>>(W);
    k_main<<<128, 256>>>(X, mean, out);
}